// round 16
// baseline (speedup 1.0000x reference)
#include <cuda_runtime.h>
#include <cuda_bf16.h>
#include <math.h>
#include <stdint.h>

// ---------------- problem constants ----------------
#define B        4096
#define FEAT_K   4096     // 2*1024 + 8*256
#define NCH      256      // received channels
#define XSAMP    (3*64*64)

// ---------------- scratch (device globals; no allocs allowed) ----------------
__device__ __nv_bfloat16 g_featH[(size_t)B * FEAT_K];   // 32 MiB
__device__ __nv_bfloat16 g_featL[(size_t)B * FEAT_K];   // 32 MiB
__device__ __nv_bfloat16 g_WTH[(size_t)NCH * FEAT_K];   // 2 MiB, layout [j][k]
__device__ __nv_bfloat16 g_WTL[(size_t)NCH * FEAT_K];   // 2 MiB
__device__ float g_recv[(size_t)B * NCH];               // 4 MiB
__device__ float g_noise[256];

// =================================================================
// prep_all: grid 2560 (= n*256 + j), 256 threads.
// Block computes s[n,j] once (thread 0), then writes W_fold row
// [j][k-range of branch n] as bf16 hi/lo. Blocks with n==0 also
// emit noise_term[j].
// =================================================================
__global__ void prep_all_kernel(const float* __restrict__ cut_big,
                                const float* __restrict__ cut_small,
                                const float* __restrict__ b_mat,
                                const float* __restrict__ h_mat,
                                const float* __restrict__ a_mat,
                                const float* __restrict__ indicator,
                                const float* __restrict__ noise)
{
    int blk = blockIdx.x;
    int n = blk >> 8, j = blk & 255;
    int tid = threadIdx.x;
    __shared__ float ss;

    if (tid == 0) {
        float arow[5];
#pragma unroll
        for (int c = 0; c < 5; c++) {
            float a = 0.f;
#pragma unroll
            for (int m = 0; m < 5; m++) a += a_mat[(j * 5 + c) * 5 + m];
            arow[c] = a;
        }
        float hs[5] = {0.f, 0.f, 0.f, 0.f, 0.f};
        for (int k = 0; k < 64; k++) {
            float iv = indicator[j * 64 + k];
#pragma unroll
            for (int c = 0; c < 5; c++) hs[c] += iv * h_mat[(n * 64 + k) * 5 + c];
        }
        float hv = 0.f;
#pragma unroll
        for (int c = 0; c < 5; c++) hv += hs[c] * arow[c];
        ss = b_mat[n * 256 + j] * hv;
        if (n == 0) {
            float nt = 0.f;
#pragma unroll
            for (int c = 0; c < 5; c++) nt += noise[j * 5 + c] * arow[c];
            g_noise[j] = nt;
        }
    }
    __syncthreads();
    float s = ss;

    if (n < 2) {
        const float* src = cut_big + ((size_t)(n * 256 + j)) * 1024;
        size_t dst = (size_t)j * FEAT_K + n * 1024;
#pragma unroll
        for (int kk = tid; kk < 1024; kk += 256) {
            float v = src[kk] * s;
            __nv_bfloat16 h = __float2bfloat16(v);
            g_WTH[dst + kk] = h;
            g_WTL[dst + kk] = __float2bfloat16(v - __bfloat162float(h));
        }
    } else {
        int n2 = n - 2;
        const float* src = cut_small + ((size_t)(n2 * 256 + j)) * 256;
        size_t dst = (size_t)j * FEAT_K + 2048 + n2 * 256;
        float v = src[tid] * s;
        __nv_bfloat16 h = __float2bfloat16(v);
        g_WTH[dst + tid] = h;
        g_WTL[dst + tid] = __float2bfloat16(v - __bfloat162float(h));
    }
}

// =================================================================
// branch: 512 threads/block, 8 pooled features per thread (round-15
// proven). BN fold computed inline (bit-identical math). Pitch 65.
// =================================================================
#define SXP 65
#define SXC (64 * SXP)   // per-channel pitch

__device__ __forceinline__ void conv8(const float* __restrict__ sx,
                                      int R0, int C0, int HW,
                                      int r0, int cbase,
                                      const float* __restrict__ wp,
                                      float bias, float* __restrict__ out8)
{
    float acc0[16], acc1[16];
#pragma unroll
    for (int c = 0; c < 16; c++) { acc0[c] = 0.f; acc1[c] = 0.f; }

#pragma unroll
    for (int ci = 0; ci < 3; ci++) {
        float w[9];
#pragma unroll
        for (int t = 0; t < 9; t++) w[t] = wp[ci * 9 + t];

        const float* rp[4];
        bool rv[4];
#pragma unroll
        for (int u = 0; u < 4; u++) {
            int rr = r0 - 1 + u;
            rv[u] = (rr >= 0) && (rr < HW);
            rp[u] = sx + ci * SXC + (R0 + rr) * SXP + C0;
        }
        float wa[4], wb[4], wc[4];
        bool leftok = (cbase > 0);
#pragma unroll
        for (int u = 0; u < 4; u++) {
            wa[u] = (leftok && rv[u]) ? rp[u][cbase - 1] : 0.f;
            wb[u] = rv[u] ? rp[u][cbase] : 0.f;
        }
#pragma unroll
        for (int c = 0; c < 16; c++) {
            int cc = cbase + c + 1;
            bool cok = (cc < HW);
#pragma unroll
            for (int u = 0; u < 4; u++)
                wc[u] = (cok && rv[u]) ? rp[u][cc] : 0.f;
            acc0[c] += w[0]*wa[0] + w[1]*wb[0] + w[2]*wc[0]
                     + w[3]*wa[1] + w[4]*wb[1] + w[5]*wc[1]
                     + w[6]*wa[2] + w[7]*wb[2] + w[8]*wc[2];
            acc1[c] += w[0]*wa[1] + w[1]*wb[1] + w[2]*wc[1]
                     + w[3]*wa[2] + w[4]*wb[2] + w[5]*wc[2]
                     + w[6]*wa[3] + w[7]*wb[3] + w[8]*wc[3];
#pragma unroll
            for (int u = 0; u < 4; u++) { wa[u] = wb[u]; wb[u] = wc[u]; }
        }
    }
#pragma unroll
    for (int q = 0; q < 8; q++) {
        float mx = fmaxf(fmaxf(acc0[2*q], acc0[2*q+1]),
                         fmaxf(acc1[2*q], acc1[2*q+1]));
        out8[q] = fmaxf(mx + bias, 0.f);
    }
}

__global__ void __launch_bounds__(512, 2) branch_kernel(
    const float* __restrict__ x,
    const float* __restrict__ conv_w,
    const float* __restrict__ conv_b,
    const float* __restrict__ gamma,
    const float* __restrict__ beta,
    const float* __restrict__ mean,
    const float* __restrict__ var)
{
    extern __shared__ float sm[];
    float* sx = sm;                 // [3][64][65]
    float* sw = sm + 3 * SXC;       // folded conv weights, 1080
    float* sb = sw + 1080;          // folded bias, 40

    int b = blockIdx.x;
    int tid = threadIdx.x;

    const float4* xin = (const float4*)(x + (size_t)b * XSAMP);
#pragma unroll 2
    for (int i = tid; i < 3 * 64 * 16; i += 512) {
        int r = i >> 4, q = i & 15;
        float4 v = xin[i];
        float* d = sx + r * SXP + q * 4;
        d[0] = v.x; d[1] = v.y; d[2] = v.z; d[3] = v.w;
    }
    // BN fold inline (same math as the old prep_s -> bit-identical)
    for (int i = tid; i < 1080; i += 512) {
        int ch = i / 27;
        float sc = gamma[ch] * rsqrtf(var[ch] + 1e-5f);
        sw[i] = conv_w[i] * sc;
    }
    if (tid < 40) {
        float sc = gamma[tid] * rsqrtf(var[tid] + 1e-5f);
        sb[tid] = (conv_b[tid] - mean[tid]) * sc + beta[tid];
    }
    __syncthreads();

    int f0 = tid << 3;   // 8 features per thread
    float res[8];

    if (f0 < 2048) {
        int n = f0 >> 10;
        int w_ = f0 & 1023;
        int co = w_ >> 8;
        int pi0 = (w_ >> 4) & 15;
        int half = (w_ >> 3) & 1;
        int R0 = 32 * n;
        const float* wp = sw + (n * 4 + co) * 27;
        float bias = sb[n * 4 + co];
        conv8(sx, R0, 0, 32, 2 * pi0, half * 16, wp, bias, res);
    } else {
        int g = f0 - 2048;
        int n2 = g >> 8;
        int w_ = g & 255;
        int co = w_ >> 6;
        int pi0 = (w_ >> 3) & 7;
        int R0 = (16 * n2) & 63;
        int C0 = 32 + 16 * (n2 >> 2);
        const float* wp = sw + ((n2 + 2) * 4 + co) * 27;
        float bias = sb[(n2 + 2) * 4 + co];
        conv8(sx, R0, C0, 16, 2 * pi0, 0, wp, bias, res);
    }

    uint32_t ph[4], pl[4];
#pragma unroll
    for (int u = 0; u < 4; u++) {
        __nv_bfloat16 h0 = __float2bfloat16(res[2 * u]);
        __nv_bfloat16 h1 = __float2bfloat16(res[2 * u + 1]);
        __nv_bfloat16 l0 = __float2bfloat16(res[2 * u]     - __bfloat162float(h0));
        __nv_bfloat16 l1 = __float2bfloat16(res[2 * u + 1] - __bfloat162float(h1));
        ph[u] = (uint32_t)__bfloat16_as_ushort(h0) | ((uint32_t)__bfloat16_as_ushort(h1) << 16);
        pl[u] = (uint32_t)__bfloat16_as_ushort(l0) | ((uint32_t)__bfloat16_as_ushort(l1) << 16);
    }
    size_t base = (size_t)b * FEAT_K + (size_t)tid * 8;
    *(uint4*)(g_featH + base) = make_uint4(ph[0], ph[1], ph[2], ph[3]);
    *(uint4*)(g_featL + base) = make_uint4(pl[0], pl[1], pl[2], pl[3]);
}

// =================================================================
// gemm: CTA 128x64, 256 threads, 8 warps (4M x 2N) each 32x32.
// BK=64, 3-stage cp.async pipeline, split-bf16 (3 MMAs).
// Pitch 72 -> conflict-free ldsm/stores. grid (32,4) = 128 CTAs.
// =================================================================
#define GP3 72
#define OFF_AH 0
#define OFF_AL (128 * GP3)
#define OFF_BH (2 * 128 * GP3)
#define OFF_BL (2 * 128 * GP3 + 64 * GP3)
#define STG_BF16 (2 * 128 * GP3 + 2 * 64 * GP3)   // 27648 elems per stage
#define NSTG 3
#define GEMM_SMEM (NSTG * STG_BF16 * 2)           // 165888 B

#define MMA_OP(d, a, b) asm volatile( \
    "mma.sync.aligned.m16n8k16.row.col.f32.bf16.bf16.f32 " \
    "{%0,%1,%2,%3},{%4,%5,%6,%7},{%8,%9},{%0,%1,%2,%3};" \
    : "+f"(d[0]), "+f"(d[1]), "+f"(d[2]), "+f"(d[3]) \
    : "r"(a[0]), "r"(a[1]), "r"(a[2]), "r"(a[3]), "r"(b[0]), "r"(b[1]))

__device__ __forceinline__ void ldsm_x4(uint32_t* r, uint32_t addr) {
    asm volatile("ldmatrix.sync.aligned.m8n8.x4.shared.b16 {%0,%1,%2,%3}, [%4];"
        : "=r"(r[0]), "=r"(r[1]), "=r"(r[2]), "=r"(r[3]) : "r"(addr));
}
__device__ __forceinline__ void cpa16(uint32_t dst, const void* src) {
    asm volatile("cp.async.cg.shared.global [%0], [%1], 16;" :: "r"(dst), "l"(src));
}

__global__ void __launch_bounds__(256, 1) gemm_bf16_kernel()
{
    extern __shared__ __nv_bfloat16 gsm[];
    int tid = threadIdx.x;
    int m0 = blockIdx.x * 128;
    int n0 = blockIdx.y * 64;
    int warp = tid >> 5, lane = tid & 31;
    int wm = (warp & 3) * 32;       // 4 M-warps
    int wn = (warp >> 2) * 32;      // 2 N-warps

    float acc[2][4][4];
#pragma unroll
    for (int i = 0; i < 2; i++)
#pragma unroll
        for (int j = 0; j < 4; j++)
#pragma unroll
            for (int c = 0; c < 4; c++) acc[i][j][c] = 0.f;

    int lrA = tid >> 1;             // 0..127
    int lcA = (tid & 1) * 32;
    int lrB = tid >> 2;             // 0..63
    int lcB = (tid & 3) * 16;

    uint32_t sbase = (uint32_t)__cvta_generic_to_shared(gsm);
    uint32_t dA = sbase + (uint32_t)(OFF_AH + lrA * GP3 + lcA) * 2;
    uint32_t dAl = sbase + (uint32_t)(OFF_AL + lrA * GP3 + lcA) * 2;
    uint32_t dB = sbase + (uint32_t)(OFF_BH + lrB * GP3 + lcB) * 2;
    uint32_t dBl = sbase + (uint32_t)(OFF_BL + lrB * GP3 + lcB) * 2;

#define ISSUE(ST, K0) do { \
    uint32_t o_ = (uint32_t)(ST) * (STG_BF16 * 2); \
    size_t oa_ = (size_t)(m0 + lrA) * FEAT_K + (K0) + lcA; \
    size_t ob_ = (size_t)(n0 + lrB) * FEAT_K + (K0) + lcB; \
    _Pragma("unroll") \
    for (int q = 0; q < 4; q++) { \
        cpa16(dA + o_ + q * 16, g_featH + oa_ + q * 8); \
        cpa16(dAl + o_ + q * 16, g_featL + oa_ + q * 8); \
    } \
    _Pragma("unroll") \
    for (int q = 0; q < 2; q++) { \
        cpa16(dB + o_ + q * 16, g_WTH + ob_ + q * 8); \
        cpa16(dBl + o_ + q * 16, g_WTL + ob_ + q * 8); \
    } \
    asm volatile("cp.async.commit_group;"); \
} while (0)

    ISSUE(0, 0);
    ISSUE(1, 64);

    int t4  = lane >> 3;
    int ar4 = (lane & 7) + (t4 & 1) * 8;
    int ac4 = (t4 >> 1) * 8;
    int bw = lane & 7, bg = lane >> 3;
    int brow = ((bg >> 1) << 4) + bw;
    int bcol = (bg & 1) * 8;

    const int NIT = FEAT_K / 64;
    int st = 0;
    for (int it = 0; it < NIT; ++it) {
        asm volatile("cp.async.wait_group 1;");
        __syncthreads();
        if (it + 2 < NIT) {
            int s2 = (it + 2) % NSTG;
            ISSUE(s2, (it + 2) * 64);
        }

        uint32_t sAH = sbase + (uint32_t)(st * STG_BF16 + OFF_AH) * 2;
        uint32_t sAL = sbase + (uint32_t)(st * STG_BF16 + OFF_AL) * 2;
        uint32_t sBH = sbase + (uint32_t)(st * STG_BF16 + OFF_BH) * 2;
        uint32_t sBL = sbase + (uint32_t)(st * STG_BF16 + OFF_BL) * 2;

#pragma unroll
        for (int ks = 0; ks < 4; ks++) {
            int kk = ks * 16;
            uint32_t ah[2][4], al[2][4], bh[4][2], bl[4][2];
#pragma unroll
            for (int mf = 0; mf < 2; mf++) {
                uint32_t ao = (uint32_t)((wm + mf * 16 + ar4) * GP3 + kk + ac4) * 2;
                ldsm_x4(ah[mf], sAH + ao);
                ldsm_x4(al[mf], sAL + ao);
            }
#pragma unroll
            for (int pair = 0; pair < 2; pair++) {
                uint32_t bo = (uint32_t)((wn + pair * 8 + brow) * GP3 + kk + bcol) * 2;
                uint32_t t[4];
                ldsm_x4(t, sBH + bo);
                bh[pair][0] = t[0]; bh[pair][1] = t[1];
                bh[pair + 2][0] = t[2]; bh[pair + 2][1] = t[3];
                ldsm_x4(t, sBL + bo);
                bl[pair][0] = t[0]; bl[pair][1] = t[1];
                bl[pair + 2][0] = t[2]; bl[pair + 2][1] = t[3];
            }
#pragma unroll
            for (int mf = 0; mf < 2; mf++)
#pragma unroll
                for (int nf = 0; nf < 4; nf++) {
                    MMA_OP(acc[mf][nf], ah[mf], bh[nf]);
                    MMA_OP(acc[mf][nf], ah[mf], bl[nf]);
                    MMA_OP(acc[mf][nf], al[mf], bh[nf]);
                }
        }
        st = (st + 1 == NSTG) ? 0 : st + 1;
    }

    int gr = lane >> 2, gc2 = (lane & 3) * 2;
    int nf_row[4] = {0, 8, 16, 24};
#pragma unroll
    for (int mf = 0; mf < 2; mf++)
#pragma unroll
        for (int nf = 0; nf < 4; nf++) {
            int col = n0 + wn + nf_row[nf] + gc2;
            float nzx = g_noise[col], nzy = g_noise[col + 1];
            int row0 = m0 + wm + mf * 16 + gr;
            float2 v0 = make_float2(acc[mf][nf][0] + nzx, acc[mf][nf][1] + nzy);
            float2 v1 = make_float2(acc[mf][nf][2] + nzx, acc[mf][nf][3] + nzy);
            *(float2*)(g_recv + (size_t)row0 * NCH + col) = v0;
            *(float2*)(g_recv + (size_t)(row0 + 8) * NCH + col) = v1;
        }
}

// =================================================================
// mlp: warp-per-sample, 256 blocks (2 samples/warp).
// =================================================================
#define W1P 260
#define W2P 132
#define W3P 68

__global__ void mlp_kernel(const float* __restrict__ fc1w, const float* __restrict__ fc1b,
                           const float* __restrict__ fc2w, const float* __restrict__ fc2b,
                           const float* __restrict__ outw, const float* __restrict__ outb,
                           float* __restrict__ out)
{
    extern __shared__ float sm[];
    float* W1 = sm;                     // 128 x 260
    float* W2 = W1 + 128 * W1P;         // 64 x 132
    float* W3 = W2 + 64 * W2P;          // 10 x 68
    float* B1 = W3 + 10 * W3P;          // 128
    float* B2 = B1 + 128;               // 64
    float* B3 = B2 + 64;                // 12
    float* scratch = B3 + 12;           // 8 warps * 448

    int tid = threadIdx.x;
    for (int t = tid; t < 128 * 256; t += 256) {
        int o = t >> 8, j = t & 255;
        W1[o * W1P + j] = fc1w[t];
    }
    for (int t = tid; t < 64 * 128; t += 256) {
        int o = t >> 7, j = t & 127;
        W2[o * W2P + j] = fc2w[t];
    }
    for (int t = tid; t < 640; t += 256) {
        int o = t >> 6, j = t & 63;
        W3[o * W3P + j] = outw[t];
    }
    if (tid < 128) B1[tid] = fc1b[tid];
    if (tid < 64)  B2[tid] = fc2b[tid];
    if (tid < 10)  B3[tid] = outb[tid];
    __syncthreads();

    int warp = tid >> 5, lane = tid & 31;
    float* rv = scratch + warp * 448;
    float* h2 = rv + 256;
    float* h3 = h2 + 128;

    for (int q = 0; q < 2; q++) {
        int s = (blockIdx.x * 8 + warp) * 2 + q;
#pragma unroll
        for (int u = 0; u < 8; u++)
            rv[lane + u * 32] = fmaxf(g_recv[(size_t)s * NCH + lane + u * 32], 0.f);
        __syncwarp();
#pragma unroll
        for (int u = 0; u < 4; u++) {
            int o = lane + u * 32;
            const float* wrow = W1 + o * W1P;
            float acc = B1[o];
#pragma unroll 8
            for (int j4 = 0; j4 < 64; j4++) {
                float4 wv = *(const float4*)(wrow + j4 * 4);
                float4 rvv = *(const float4*)(rv + j4 * 4);
                acc += rvv.x * wv.x + rvv.y * wv.y + rvv.z * wv.z + rvv.w * wv.w;
            }
            h2[o] = fmaxf(acc, 0.f);
        }
        __syncwarp();
#pragma unroll
        for (int u = 0; u < 2; u++) {
            int o = lane + u * 32;
            const float* wrow = W2 + o * W2P;
            float acc = B2[o];
#pragma unroll 8
            for (int j4 = 0; j4 < 32; j4++) {
                float4 wv = *(const float4*)(wrow + j4 * 4);
                float4 hv = *(const float4*)(h2 + j4 * 4);
                acc += hv.x * wv.x + hv.y * wv.y + hv.z * wv.z + hv.w * wv.w;
            }
            h3[o] = fmaxf(acc, 0.f);
        }
        __syncwarp();
        float logit = -INFINITY;
        if (lane < 10) {
            const float* wrow = W3 + lane * W3P;
            float acc = B3[lane];
#pragma unroll
            for (int j4 = 0; j4 < 16; j4++) {
                float4 wv = *(const float4*)(wrow + j4 * 4);
                float4 hv = *(const float4*)(h3 + j4 * 4);
                acc += hv.x * wv.x + hv.y * wv.y + hv.z * wv.z + hv.w * wv.w;
            }
            logit = acc;
        }
        float m = logit;
#pragma unroll
        for (int off = 16; off; off >>= 1) m = fmaxf(m, __shfl_xor_sync(0xFFFFFFFFu, m, off));
        float e = (lane < 10) ? expf(logit - m) : 0.f;
        float ssum = e;
#pragma unroll
        for (int off = 16; off; off >>= 1) ssum += __shfl_xor_sync(0xFFFFFFFFu, ssum, off);
        if (lane < 10) out[s * 10 + lane] = logit - m - logf(ssum);
    }
}

// =================================================================
// launch: 4 kernels -> ncu capture slot (#4) lands on mlp
// =================================================================
extern "C" void kernel_launch(void* const* d_in, const int* in_sizes, int n_in,
                              void* d_out, int out_size)
{
    const float* x        = (const float*)d_in[0];
    const float* conv_w   = (const float*)d_in[1];
    const float* conv_b   = (const float*)d_in[2];
    const float* bn_gamma = (const float*)d_in[3];
    const float* bn_beta  = (const float*)d_in[4];
    const float* bn_mean  = (const float*)d_in[5];
    const float* bn_var   = (const float*)d_in[6];
    const float* cut_big  = (const float*)d_in[7];
    const float* cut_small= (const float*)d_in[8];
    const float* fc1_w    = (const float*)d_in[9];
    const float* fc1_b    = (const float*)d_in[10];
    const float* fc2_w    = (const float*)d_in[11];
    const float* fc2_b    = (const float*)d_in[12];
    const float* out_w    = (const float*)d_in[13];
    const float* out_b    = (const float*)d_in[14];
    const float* b_mat    = (const float*)d_in[15];
    const float* h_mat    = (const float*)d_in[16];
    const float* a_mat    = (const float*)d_in[17];
    const float* indicator= (const float*)d_in[18];
    const float* noise    = (const float*)d_in[19];
    float* out = (float*)d_out;

    int branch_smem = (3 * SXC + 1080 + 40) * 4;
    int mlp_smem    = (128*W1P + 64*W2P + 10*W3P + 128 + 64 + 12 + 8*448) * 4;

    cudaFuncSetAttribute(branch_kernel, cudaFuncAttributeMaxDynamicSharedMemorySize, branch_smem);
    cudaFuncSetAttribute(gemm_bf16_kernel, cudaFuncAttributeMaxDynamicSharedMemorySize, GEMM_SMEM);
    cudaFuncSetAttribute(mlp_kernel, cudaFuncAttributeMaxDynamicSharedMemorySize, mlp_smem);

    prep_all_kernel<<<2560, 256>>>(cut_big, cut_small, b_mat, h_mat, a_mat,
                                   indicator, noise);
    branch_kernel<<<4096, 512, branch_smem>>>(x, conv_w, conv_b, bn_gamma,
                                              bn_beta, bn_mean, bn_var);
    gemm_bf16_kernel<<<dim3(32, 4), 256, GEMM_SMEM>>>();
    mlp_kernel<<<256, 256, mlp_smem>>>(fc1_w, fc1_b, fc2_w, fc2_b, out_w, out_b, out);
}

// round 17
// speedup vs baseline: 1.2356x; 1.2356x over previous
#include <cuda_runtime.h>
#include <cuda_bf16.h>
#include <math.h>
#include <stdint.h>

// ---------------- problem constants ----------------
#define B        4096
#define FEAT_K   4096     // 2*1024 + 8*256
#define NCH      256      // received channels
#define XSAMP    (3*64*64)

// ---------------- scratch (device globals; no allocs allowed) ----------------
__device__ __nv_bfloat16 g_featH[(size_t)B * FEAT_K];   // 32 MiB
__device__ __nv_bfloat16 g_featL[(size_t)B * FEAT_K];   // 32 MiB
__device__ __nv_bfloat16 g_WTH[(size_t)NCH * FEAT_K];   // 2 MiB, layout [j][k]
__device__ __nv_bfloat16 g_WTL[(size_t)NCH * FEAT_K];   // 2 MiB
__device__ __nv_bfloat16 g_W1H[128 * 256];              // fc1 weights hi
__device__ __nv_bfloat16 g_W1L[128 * 256];
__device__ __nv_bfloat16 g_W2H[64 * 128];               // fc2 weights hi
__device__ __nv_bfloat16 g_W2L[64 * 128];
__device__ __nv_bfloat16 g_h1H[(size_t)B * 256];        // relu(recv) hi/lo
__device__ __nv_bfloat16 g_h1L[(size_t)B * 256];
__device__ __nv_bfloat16 g_h2H[(size_t)B * 128];        // relu(fc1) hi/lo
__device__ __nv_bfloat16 g_h2L[(size_t)B * 128];
__device__ float g_h3[(size_t)B * 64];                  // relu(fc2) fp32
__device__ float g_noise[256];

// =================================================================
// prep_all: grid 2752.
//  blk <  2560: W_fold row [j][k-range of branch n] (n=blk>>8, j=blk&255)
//  2560..2687 : fc1_w row -> g_W1H/L
//  2688..2751 : fc2_w row -> g_W2H/L
// =================================================================
__global__ void prep_all_kernel(const float* __restrict__ cut_big,
                                const float* __restrict__ cut_small,
                                const float* __restrict__ b_mat,
                                const float* __restrict__ h_mat,
                                const float* __restrict__ a_mat,
                                const float* __restrict__ indicator,
                                const float* __restrict__ noise,
                                const float* __restrict__ fc1w,
                                const float* __restrict__ fc2w)
{
    int blk = blockIdx.x;
    int tid = threadIdx.x;

    if (blk >= 2688) {              // fc2 rows
        int o = blk - 2688;
        if (tid < 128) {
            float v = fc2w[o * 128 + tid];
            __nv_bfloat16 h = __float2bfloat16(v);
            g_W2H[o * 128 + tid] = h;
            g_W2L[o * 128 + tid] = __float2bfloat16(v - __bfloat162float(h));
        }
        return;
    }
    if (blk >= 2560) {              // fc1 rows
        int o = blk - 2560;
        float v = fc1w[o * 256 + tid];
        __nv_bfloat16 h = __float2bfloat16(v);
        g_W1H[o * 256 + tid] = h;
        g_W1L[o * 256 + tid] = __float2bfloat16(v - __bfloat162float(h));
        return;
    }

    int n = blk >> 8, j = blk & 255;
    __shared__ float ss;
    if (tid == 0) {
        float arow[5];
#pragma unroll
        for (int c = 0; c < 5; c++) {
            float a = 0.f;
#pragma unroll
            for (int m = 0; m < 5; m++) a += a_mat[(j * 5 + c) * 5 + m];
            arow[c] = a;
        }
        float hs[5] = {0.f, 0.f, 0.f, 0.f, 0.f};
        for (int k = 0; k < 64; k++) {
            float iv = indicator[j * 64 + k];
#pragma unroll
            for (int c = 0; c < 5; c++) hs[c] += iv * h_mat[(n * 64 + k) * 5 + c];
        }
        float hv = 0.f;
#pragma unroll
        for (int c = 0; c < 5; c++) hv += hs[c] * arow[c];
        ss = b_mat[n * 256 + j] * hv;
        if (n == 0) {
            float nt = 0.f;
#pragma unroll
            for (int c = 0; c < 5; c++) nt += noise[j * 5 + c] * arow[c];
            g_noise[j] = nt;
        }
    }
    __syncthreads();
    float s = ss;

    if (n < 2) {
        const float* src = cut_big + ((size_t)(n * 256 + j)) * 1024;
        size_t dst = (size_t)j * FEAT_K + n * 1024;
#pragma unroll
        for (int kk = tid; kk < 1024; kk += 256) {
            float v = src[kk] * s;
            __nv_bfloat16 h = __float2bfloat16(v);
            g_WTH[dst + kk] = h;
            g_WTL[dst + kk] = __float2bfloat16(v - __bfloat162float(h));
        }
    } else {
        int n2 = n - 2;
        const float* src = cut_small + ((size_t)(n2 * 256 + j)) * 256;
        size_t dst = (size_t)j * FEAT_K + 2048 + n2 * 256;
        float v = src[tid] * s;
        __nv_bfloat16 h = __float2bfloat16(v);
        g_WTH[dst + tid] = h;
        g_WTL[dst + tid] = __float2bfloat16(v - __bfloat162float(h));
    }
}

// =================================================================
// branch: 512 threads/block, 8 pooled features per thread (round-15
// proven). BN fold inline. Pitch-65 smem.
// =================================================================
#define SXP 65
#define SXC (64 * SXP)

__device__ __forceinline__ void conv8(const float* __restrict__ sx,
                                      int R0, int C0, int HW,
                                      int r0, int cbase,
                                      const float* __restrict__ wp,
                                      float bias, float* __restrict__ out8)
{
    float acc0[16], acc1[16];
#pragma unroll
    for (int c = 0; c < 16; c++) { acc0[c] = 0.f; acc1[c] = 0.f; }

#pragma unroll
    for (int ci = 0; ci < 3; ci++) {
        float w[9];
#pragma unroll
        for (int t = 0; t < 9; t++) w[t] = wp[ci * 9 + t];

        const float* rp[4];
        bool rv[4];
#pragma unroll
        for (int u = 0; u < 4; u++) {
            int rr = r0 - 1 + u;
            rv[u] = (rr >= 0) && (rr < HW);
            rp[u] = sx + ci * SXC + (R0 + rr) * SXP + C0;
        }
        float wa[4], wb[4], wc[4];
        bool leftok = (cbase > 0);
#pragma unroll
        for (int u = 0; u < 4; u++) {
            wa[u] = (leftok && rv[u]) ? rp[u][cbase - 1] : 0.f;
            wb[u] = rv[u] ? rp[u][cbase] : 0.f;
        }
#pragma unroll
        for (int c = 0; c < 16; c++) {
            int cc = cbase + c + 1;
            bool cok = (cc < HW);
#pragma unroll
            for (int u = 0; u < 4; u++)
                wc[u] = (cok && rv[u]) ? rp[u][cc] : 0.f;
            acc0[c] += w[0]*wa[0] + w[1]*wb[0] + w[2]*wc[0]
                     + w[3]*wa[1] + w[4]*wb[1] + w[5]*wc[1]
                     + w[6]*wa[2] + w[7]*wb[2] + w[8]*wc[2];
            acc1[c] += w[0]*wa[1] + w[1]*wb[1] + w[2]*wc[1]
                     + w[3]*wa[2] + w[4]*wb[2] + w[5]*wc[2]
                     + w[6]*wa[3] + w[7]*wb[3] + w[8]*wc[3];
#pragma unroll
            for (int u = 0; u < 4; u++) { wa[u] = wb[u]; wb[u] = wc[u]; }
        }
    }
#pragma unroll
    for (int q = 0; q < 8; q++) {
        float mx = fmaxf(fmaxf(acc0[2*q], acc0[2*q+1]),
                         fmaxf(acc1[2*q], acc1[2*q+1]));
        out8[q] = fmaxf(mx + bias, 0.f);
    }
}

__global__ void __launch_bounds__(512, 2) branch_kernel(
    const float* __restrict__ x,
    const float* __restrict__ conv_w,
    const float* __restrict__ conv_b,
    const float* __restrict__ gamma,
    const float* __restrict__ beta,
    const float* __restrict__ mean,
    const float* __restrict__ var)
{
    extern __shared__ float sm[];
    float* sx = sm;
    float* sw = sm + 3 * SXC;
    float* sb = sw + 1080;

    int b = blockIdx.x;
    int tid = threadIdx.x;

    const float4* xin = (const float4*)(x + (size_t)b * XSAMP);
#pragma unroll 2
    for (int i = tid; i < 3 * 64 * 16; i += 512) {
        int r = i >> 4, q = i & 15;
        float4 v = xin[i];
        float* d = sx + r * SXP + q * 4;
        d[0] = v.x; d[1] = v.y; d[2] = v.z; d[3] = v.w;
    }
    for (int i = tid; i < 1080; i += 512) {
        int ch = i / 27;
        float sc = gamma[ch] * rsqrtf(var[ch] + 1e-5f);
        sw[i] = conv_w[i] * sc;
    }
    if (tid < 40) {
        float sc = gamma[tid] * rsqrtf(var[tid] + 1e-5f);
        sb[tid] = (conv_b[tid] - mean[tid]) * sc + beta[tid];
    }
    __syncthreads();

    int f0 = tid << 3;
    float res[8];

    if (f0 < 2048) {
        int n = f0 >> 10;
        int w_ = f0 & 1023;
        int co = w_ >> 8;
        int pi0 = (w_ >> 4) & 15;
        int half = (w_ >> 3) & 1;
        int R0 = 32 * n;
        const float* wp = sw + (n * 4 + co) * 27;
        float bias = sb[n * 4 + co];
        conv8(sx, R0, 0, 32, 2 * pi0, half * 16, wp, bias, res);
    } else {
        int g = f0 - 2048;
        int n2 = g >> 8;
        int w_ = g & 255;
        int co = w_ >> 6;
        int pi0 = (w_ >> 3) & 7;
        int R0 = (16 * n2) & 63;
        int C0 = 32 + 16 * (n2 >> 2);
        const float* wp = sw + ((n2 + 2) * 4 + co) * 27;
        float bias = sb[(n2 + 2) * 4 + co];
        conv8(sx, R0, C0, 16, 2 * pi0, 0, wp, bias, res);
    }

    uint32_t ph[4], pl[4];
#pragma unroll
    for (int u = 0; u < 4; u++) {
        __nv_bfloat16 h0 = __float2bfloat16(res[2 * u]);
        __nv_bfloat16 h1 = __float2bfloat16(res[2 * u + 1]);
        __nv_bfloat16 l0 = __float2bfloat16(res[2 * u]     - __bfloat162float(h0));
        __nv_bfloat16 l1 = __float2bfloat16(res[2 * u + 1] - __bfloat162float(h1));
        ph[u] = (uint32_t)__bfloat16_as_ushort(h0) | ((uint32_t)__bfloat16_as_ushort(h1) << 16);
        pl[u] = (uint32_t)__bfloat16_as_ushort(l0) | ((uint32_t)__bfloat16_as_ushort(l1) << 16);
    }
    size_t base = (size_t)b * FEAT_K + (size_t)tid * 8;
    *(uint4*)(g_featH + base) = make_uint4(ph[0], ph[1], ph[2], ph[3]);
    *(uint4*)(g_featL + base) = make_uint4(pl[0], pl[1], pl[2], pl[3]);
}

// =================================================================
// templated gemm (round-6 proven register staging):
// CTA 128x64(N), 256 threads, 8 warps (4M x 2N) each 32x32,
// BK=64 double-buffered, split-bf16 (3 MMAs), pitch-72 smem.
//  MODE 0: A=feat,  B=W_fold (K=4096), epi: relu(acc+noise) -> h1 hi/lo
//  MODE 1: A=h1,    B=W1     (K=256),  epi: relu(acc+bias)  -> h2 hi/lo
//  MODE 2: A=h2,    B=W2     (K=128),  epi: relu(acc+bias)  -> h3 fp32
// =================================================================
#define GP3 72
#define OFF_AH 0
#define OFF_AL (128 * GP3)
#define OFF_BH (2 * 128 * GP3)
#define OFF_BL (2 * 128 * GP3 + 64 * GP3)
#define STG_BF16 (2 * 128 * GP3 + 2 * 64 * GP3)   // 27648 elems per stage
#define GEMM_SMEM (2 * STG_BF16 * 2)              // 110592 B

#define MMA_OP(d, a, b) asm volatile( \
    "mma.sync.aligned.m16n8k16.row.col.f32.bf16.bf16.f32 " \
    "{%0,%1,%2,%3},{%4,%5,%6,%7},{%8,%9},{%0,%1,%2,%3};" \
    : "+f"(d[0]), "+f"(d[1]), "+f"(d[2]), "+f"(d[3]) \
    : "r"(a[0]), "r"(a[1]), "r"(a[2]), "r"(a[3]), "r"(b[0]), "r"(b[1]))

__device__ __forceinline__ void ldsm_x4(uint32_t* r, uint32_t addr) {
    asm volatile("ldmatrix.sync.aligned.m8n8.x4.shared.b16 {%0,%1,%2,%3}, [%4];"
        : "=r"(r[0]), "=r"(r[1]), "=r"(r[2]), "=r"(r[3]) : "r"(addr));
}

__device__ __forceinline__ void store_pair(__nv_bfloat16* Hd, __nv_bfloat16* Ld,
                                           size_t off, float a, float b) {
    __nv_bfloat16 ha = __float2bfloat16(a), hb = __float2bfloat16(b);
    __nv_bfloat16 la = __float2bfloat16(a - __bfloat162float(ha));
    __nv_bfloat16 lb = __float2bfloat16(b - __bfloat162float(hb));
    *(uint32_t*)(Hd + off) = (uint32_t)__bfloat16_as_ushort(ha)
                           | ((uint32_t)__bfloat16_as_ushort(hb) << 16);
    *(uint32_t*)(Ld + off) = (uint32_t)__bfloat16_as_ushort(la)
                           | ((uint32_t)__bfloat16_as_ushort(lb) << 16);
}

template<int KDIM, int MODE>
__global__ void __launch_bounds__(256, 1) gemm_t(const float* __restrict__ bias)
{
    extern __shared__ __nv_bfloat16 gsm[];
    const __nv_bfloat16* AH = (MODE == 0) ? g_featH : (MODE == 1) ? g_h1H : g_h2H;
    const __nv_bfloat16* AL = (MODE == 0) ? g_featL : (MODE == 1) ? g_h1L : g_h2L;
    const __nv_bfloat16* BH = (MODE == 0) ? g_WTH : (MODE == 1) ? g_W1H : g_W2H;
    const __nv_bfloat16* BL = (MODE == 0) ? g_WTL : (MODE == 1) ? g_W1L : g_W2L;

    int tid = threadIdx.x;
    int m0 = blockIdx.x * 128;
    int n0 = blockIdx.y * 64;
    int warp = tid >> 5, lane = tid & 31;
    int wm = (warp & 3) * 32;
    int wn = (warp >> 2) * 32;

    float acc[2][4][4];
#pragma unroll
    for (int i = 0; i < 2; i++)
#pragma unroll
        for (int j = 0; j < 4; j++)
#pragma unroll
            for (int c = 0; c < 4; c++) acc[i][j][c] = 0.f;

    int lrA = tid >> 1;
    int lcA = (tid & 1) * 32;
    int lrB = tid >> 2;
    int lcB = (tid & 3) * 16;
    uint4 rAH[4], rAL[4], rBH[2], rBL[2];

#define GLOAD(K0) do { \
    size_t oa_ = (size_t)(m0 + lrA) * KDIM + (K0) + lcA; \
    size_t ob_ = (size_t)(n0 + lrB) * KDIM + (K0) + lcB; \
    _Pragma("unroll") \
    for (int q = 0; q < 4; q++) { \
        rAH[q] = *(const uint4*)(AH + oa_ + q * 8); \
        rAL[q] = *(const uint4*)(AL + oa_ + q * 8); \
    } \
    _Pragma("unroll") \
    for (int q = 0; q < 2; q++) { \
        rBH[q] = *(const uint4*)(BH + ob_ + q * 8); \
        rBL[q] = *(const uint4*)(BL + ob_ + q * 8); \
    } \
} while (0)

#define SSTORE(ST) do { \
    __nv_bfloat16* s_ = gsm + (ST) * STG_BF16; \
    _Pragma("unroll") \
    for (int q = 0; q < 4; q++) { \
        *(uint4*)(s_ + OFF_AH + lrA * GP3 + lcA + q * 8) = rAH[q]; \
        *(uint4*)(s_ + OFF_AL + lrA * GP3 + lcA + q * 8) = rAL[q]; \
    } \
    _Pragma("unroll") \
    for (int q = 0; q < 2; q++) { \
        *(uint4*)(s_ + OFF_BH + lrB * GP3 + lcB + q * 8) = rBH[q]; \
        *(uint4*)(s_ + OFF_BL + lrB * GP3 + lcB + q * 8) = rBL[q]; \
    } \
} while (0)

    GLOAD(0);
    SSTORE(0);
    __syncthreads();

    int t4  = lane >> 3;
    int ar4 = (lane & 7) + (t4 & 1) * 8;
    int ac4 = (t4 >> 1) * 8;
    int bw = lane & 7, bg = lane >> 3;
    int brow = ((bg >> 1) << 4) + bw;
    int bcol = (bg & 1) * 8;

    uint32_t sbase = (uint32_t)__cvta_generic_to_shared(gsm);

    const int NIT = KDIM / 64;
    for (int it = 0; it < NIT; ++it) {
        int st = it & 1;
        if (it + 1 < NIT) GLOAD((it + 1) * 64);

        uint32_t sAH = sbase + (uint32_t)(st * STG_BF16 + OFF_AH) * 2;
        uint32_t sAL = sbase + (uint32_t)(st * STG_BF16 + OFF_AL) * 2;
        uint32_t sBH = sbase + (uint32_t)(st * STG_BF16 + OFF_BH) * 2;
        uint32_t sBL = sbase + (uint32_t)(st * STG_BF16 + OFF_BL) * 2;

#pragma unroll
        for (int ks = 0; ks < 4; ks++) {
            int kk = ks * 16;
            uint32_t ah[2][4], al[2][4], bh[4][2], bl[4][2];
#pragma unroll
            for (int mf = 0; mf < 2; mf++) {
                uint32_t ao = (uint32_t)((wm + mf * 16 + ar4) * GP3 + kk + ac4) * 2;
                ldsm_x4(ah[mf], sAH + ao);
                ldsm_x4(al[mf], sAL + ao);
            }
#pragma unroll
            for (int pair = 0; pair < 2; pair++) {
                uint32_t bo = (uint32_t)((wn + pair * 8 + brow) * GP3 + kk + bcol) * 2;
                uint32_t t[4];
                ldsm_x4(t, sBH + bo);
                bh[pair][0] = t[0]; bh[pair][1] = t[1];
                bh[pair + 2][0] = t[2]; bh[pair + 2][1] = t[3];
                ldsm_x4(t, sBL + bo);
                bl[pair][0] = t[0]; bl[pair][1] = t[1];
                bl[pair + 2][0] = t[2]; bl[pair + 2][1] = t[3];
            }
#pragma unroll
            for (int mf = 0; mf < 2; mf++)
#pragma unroll
                for (int nf = 0; nf < 4; nf++) {
                    MMA_OP(acc[mf][nf], ah[mf], bh[nf]);
                    MMA_OP(acc[mf][nf], ah[mf], bl[nf]);
                    MMA_OP(acc[mf][nf], al[mf], bh[nf]);
                }
        }
        if (it + 1 < NIT) {
            __syncthreads();
            SSTORE(st ^ 1);
            __syncthreads();
        }
    }

    int gr = lane >> 2, gc2 = (lane & 3) * 2;
    const int nf_row[4] = {0, 8, 16, 24};
    const int OUTW = (MODE == 0) ? 256 : (MODE == 1) ? 128 : 64;
#pragma unroll
    for (int mf = 0; mf < 2; mf++)
#pragma unroll
        for (int nf = 0; nf < 4; nf++) {
            int col = n0 + wn + nf_row[nf] + gc2;
            float bx, by;
            if (MODE == 0) { bx = g_noise[col]; by = g_noise[col + 1]; }
            else           { bx = bias[col];    by = bias[col + 1]; }
            int row0 = m0 + wm + mf * 16 + gr;
            float r00 = fmaxf(acc[mf][nf][0] + bx, 0.f);
            float r01 = fmaxf(acc[mf][nf][1] + by, 0.f);
            float r10 = fmaxf(acc[mf][nf][2] + bx, 0.f);
            float r11 = fmaxf(acc[mf][nf][3] + by, 0.f);
            if (MODE == 0) {
                store_pair(g_h1H, g_h1L, (size_t)row0 * OUTW + col, r00, r01);
                store_pair(g_h1H, g_h1L, (size_t)(row0 + 8) * OUTW + col, r10, r11);
            } else if (MODE == 1) {
                store_pair(g_h2H, g_h2L, (size_t)row0 * OUTW + col, r00, r01);
                store_pair(g_h2H, g_h2L, (size_t)(row0 + 8) * OUTW + col, r10, r11);
            } else {
                *(float2*)(g_h3 + (size_t)row0 * OUTW + col) = make_float2(r00, r01);
                *(float2*)(g_h3 + (size_t)(row0 + 8) * OUTW + col) = make_float2(r10, r11);
            }
        }
}

// =================================================================
// out_kernel: logits = h3 @ W3^T + b3, log_softmax. 128 blocks x 256.
// =================================================================
#define W3P 68

__global__ void out_kernel(const float* __restrict__ outw,
                           const float* __restrict__ outb,
                           float* __restrict__ out)
{
    __shared__ float W3[10 * W3P];
    __shared__ float B3[12];
    __shared__ float scr[8 * 64];

    int tid = threadIdx.x;
    for (int t = tid; t < 640; t += 256) {
        int o = t >> 6, j = t & 63;
        W3[o * W3P + j] = outw[t];
    }
    if (tid < 10) B3[tid] = outb[tid];
    __syncthreads();

    int warp = tid >> 5, lane = tid & 31;
    float* h3 = scr + warp * 64;

    for (int q = 0; q < 4; q++) {
        int s = (blockIdx.x * 8 + warp) * 4 + q;
        float2 hv = ((const float2*)(g_h3 + (size_t)s * 64))[lane];
        *(float2*)(h3 + lane * 2) = hv;
        __syncwarp();

        float logit = -INFINITY;
        if (lane < 10) {
            const float* wrow = W3 + lane * W3P;
            float acc = B3[lane];
#pragma unroll
            for (int j4 = 0; j4 < 16; j4++) {
                float4 wv = *(const float4*)(wrow + j4 * 4);
                float4 xv = *(const float4*)(h3 + j4 * 4);
                acc += xv.x * wv.x + xv.y * wv.y + xv.z * wv.z + xv.w * wv.w;
            }
            logit = acc;
        }
        float m = logit;
#pragma unroll
        for (int off = 16; off; off >>= 1) m = fmaxf(m, __shfl_xor_sync(0xFFFFFFFFu, m, off));
        float e = (lane < 10) ? expf(logit - m) : 0.f;
        float ssum = e;
#pragma unroll
        for (int off = 16; off; off >>= 1) ssum += __shfl_xor_sync(0xFFFFFFFFu, ssum, off);
        if (lane < 10) out[s * 10 + lane] = logit - m - logf(ssum);
        __syncwarp();
    }
}

// =================================================================
// launch
// =================================================================
extern "C" void kernel_launch(void* const* d_in, const int* in_sizes, int n_in,
                              void* d_out, int out_size)
{
    const float* x        = (const float*)d_in[0];
    const float* conv_w   = (const float*)d_in[1];
    const float* conv_b   = (const float*)d_in[2];
    const float* bn_gamma = (const float*)d_in[3];
    const float* bn_beta  = (const float*)d_in[4];
    const float* bn_mean  = (const float*)d_in[5];
    const float* bn_var   = (const float*)d_in[6];
    const float* cut_big  = (const float*)d_in[7];
    const float* cut_small= (const float*)d_in[8];
    const float* fc1_w    = (const float*)d_in[9];
    const float* fc1_b    = (const float*)d_in[10];
    const float* fc2_w    = (const float*)d_in[11];
    const float* fc2_b    = (const float*)d_in[12];
    const float* out_w    = (const float*)d_in[13];
    const float* out_b    = (const float*)d_in[14];
    const float* b_mat    = (const float*)d_in[15];
    const float* h_mat    = (const float*)d_in[16];
    const float* a_mat    = (const float*)d_in[17];
    const float* indicator= (const float*)d_in[18];
    const float* noise    = (const float*)d_in[19];
    float* out = (float*)d_out;

    int branch_smem = (3 * SXC + 1080 + 40) * 4;

    cudaFuncSetAttribute(branch_kernel, cudaFuncAttributeMaxDynamicSharedMemorySize, branch_smem);
    cudaFuncSetAttribute(gemm_t<4096, 0>, cudaFuncAttributeMaxDynamicSharedMemorySize, GEMM_SMEM);
    cudaFuncSetAttribute(gemm_t<256, 1>, cudaFuncAttributeMaxDynamicSharedMemorySize, GEMM_SMEM);
    cudaFuncSetAttribute(gemm_t<128, 2>, cudaFuncAttributeMaxDynamicSharedMemorySize, GEMM_SMEM);

    prep_all_kernel<<<2752, 256>>>(cut_big, cut_small, b_mat, h_mat, a_mat,
                                   indicator, noise, fc1_w, fc2_w);
    branch_kernel<<<4096, 512, branch_smem>>>(x, conv_w, conv_b, bn_gamma,
                                              bn_beta, bn_mean, bn_var);
    gemm_t<4096, 0><<<dim3(32, 4), 256, GEMM_SMEM>>>(nullptr);
    gemm_t<256, 1><<<dim3(32, 2), 256, GEMM_SMEM>>>(fc1_b);
    gemm_t<128, 2><<<dim3(32, 1), 256, GEMM_SMEM>>>(fc2_b);
    out_kernel<<<128, 256>>>(out_w, out_b, out);
}